// round 11
// baseline (speedup 1.0000x reference)
#include <cuda_runtime.h>
#include <cuda_fp16.h>
#include <cstdint>

// Problem constants.
#define NSLICE 32      // B*KI = 8*4
#define NN     2048    // nodes per slice
#define IW     32
#define OW     32
#define NCHUNK 4
#define SL_PER_CHUNK (NSLICE / NCHUNK)   // 8

// exp(-sq/2) = exp2(C1 * sq), C1 = -1/(2 ln 2)
#define C1   (-0.7213475204444817f)
#define M2C1 ( 1.4426950408889634f)   // -2*C1
#define WLSCALE    4096.0f
#define INV_WLSCALE (1.0f / 4096.0f)

// Scratch (device globals: allocation-free contract).
__device__ float g_inv_d2[NSLICE * NN];
// wl as packed fp16x2 (scaled), layout per chunk16:
// [slice][chunk16(128)][half(2)][rlane(32)][word(4)]
//   half0 words = {nb0,h0},{nb0,h1},{nb1,h0},{nb1,h1}; half1 = nb2, nb3.
__device__ unsigned g_wlh[(size_t)NSLICE * 128 * 256];

// ---------------------------------------------------------------------------
// PTX helpers
// ---------------------------------------------------------------------------
__device__ __forceinline__ float ex2f(float x) {
    float y; asm("ex2.approx.f32 %0, %1;" : "=f"(y) : "f"(x)); return y;
}
__device__ __forceinline__ unsigned pack_f16(float lo, float hi) {
    unsigned d;
    asm("cvt.rn.f16x2.f32 %0, %1, %2;" : "=r"(d) : "f"(hi), "f"(lo));
    return d;
}
__device__ __forceinline__ unsigned pack2h(__half lo, __half hi) {
    return ((unsigned)__half_as_ushort(hi) << 16) | __half_as_ushort(lo);
}
// product/geometry MMA accumulate form: C += A(16x16)*B(16x8), fp16 -> fp32
__device__ __forceinline__ void mma_f16(float* c, unsigned a0, unsigned a1,
                                        unsigned a2, unsigned a3,
                                        unsigned b0, unsigned b1) {
    asm volatile(
        "mma.sync.aligned.m16n8k16.row.col.f32.f16.f16.f32 "
        "{%0,%1,%2,%3}, {%4,%5,%6,%7}, {%8,%9}, {%0,%1,%2,%3};"
        : "+f"(c[0]), "+f"(c[1]), "+f"(c[2]), "+f"(c[3])
        : "r"(a0), "r"(a1), "r"(a2), "r"(a3), "r"(b0), "r"(b1));
}
// geometry MMA with separate C (init form): D = A*B + C
__device__ __forceinline__ void mma_f16_init(
    float& d0, float& d1, float& d2, float& d3,
    unsigned a0, unsigned a1, unsigned a2, unsigned a3,
    unsigned b0, unsigned b1,
    float c0, float c1, float c2, float c3) {
    asm volatile(
        "mma.sync.aligned.m16n8k16.row.col.f32.f16.f16.f32 "
        "{%0,%1,%2,%3}, {%4,%5,%6,%7}, {%8,%9}, {%10,%11,%12,%13};"
        : "=f"(d0), "=f"(d1), "=f"(d2), "=f"(d3)
        : "r"(a0), "r"(a1), "r"(a2), "r"(a3), "r"(b0), "r"(b1),
          "f"(c0), "f"(c1), "f"(c2), "f"(c3));
}
__device__ __forceinline__ void cp_async16(uint32_t dst, const void* src) {
    asm volatile("cp.async.cg.shared.global [%0], [%1], 16;" :: "r"(dst), "l"(src));
}

// ---------------------------------------------------------------------------
// Geometry staging: per node j, fp16 two-term splits packed as 4 u32 pairs:
//  pair0 = (xh, yh), pair1 = (zh, csh), pair2 = (xl, yl), pair3 = (zl, csl)
// layout geom[oct(256)][pair(4)][j8(8)] -> 32 u32 per octet (32 KB total).
// ---------------------------------------------------------------------------
__device__ __forceinline__ void stage_geom(const float* __restrict__ p,
                                           unsigned* geom, int tid, int nt) {
    for (int n = tid; n < NN; n += nt) {
        float x = p[3 * n + 0], y = p[3 * n + 1], z = p[3 * n + 2];
        float cs = C1 * (x * x + y * y + z * z);
        __half xh = __float2half_rn(x), yh = __float2half_rn(y);
        __half zh = __float2half_rn(z), ch = __float2half_rn(cs);
        float xl = x - __half2float(xh), yl = y - __half2float(yh);
        float zl = z - __half2float(zh), cl = cs - __half2float(ch);
        int base = ((n >> 3) << 5) + (n & 7);
        geom[base + 0]  = pack2h(xh, yh);
        geom[base + 8]  = pack2h(zh, ch);
        geom[base + 16] = pack_f16(xl, yl);
        geom[base + 24] = pack_f16(zl, cl);
    }
}

// Row-side A-fragment component for this thread's tg slot.
__device__ __forceinline__ unsigned make_afrag(float x, float y, float z, int tg) {
    float qx = M2C1 * x, qy = M2C1 * y, qz = M2C1 * z;
    __half qxh = __float2half_rn(qx), qyh = __float2half_rn(qy);
    __half qzh = __float2half_rn(qz);
    if (tg == 0) return pack2h(qxh, qyh);
    if (tg == 1) return pack2h(qzh, __float2half_rn(1.0f));
    float qxl = qx - __half2float(qxh), qyl = qy - __half2float(qyh);
    float qzl = qz - __half2float(qzh);
    if (tg == 2) return pack_f16(qxl, qyl);
    return pack_f16(qzl, 1.0f);
}

// Per-octet geometry B-fragment from packed pairs.
__device__ __forceinline__ void geom_bfrag(const unsigned* geom, int oct, int off,
                                           unsigned is3, unsigned odd,
                                           unsigned& b0, unsigned& b1) {
    unsigned pa = geom[oct * 32 + off];        // pair0 or pair1
    unsigned pb = geom[oct * 32 + 16 + off];   // pair2 or pair3
    b0 = is3 ? __byte_perm(pa, pb, 0x7610) : pa;   // tg3: (zh, csl)
    b1 = odd ? (pb & 0x0000FFFFu) : pb;            // odd tg: zero hi (cs slot)
}

// ---------------------------------------------------------------------------
// Pass A (fused): degrees via split-fp16 geometry MMA, then wl epilogue.
// 64 blocks x 512 thr per 8-slice chunk; block owns 256 rows.
// ---------------------------------------------------------------------------
__global__ void __launch_bounds__(512) deg_wl_kernel(
    const float* __restrict__ pos, const float* __restrict__ w,
    const float* __restrict__ lin_w, float* __restrict__ inv_d2,
    unsigned* __restrict__ wlh, int slice_base) {
    __shared__ unsigned geom[256 * 32];   // 32 KB
    __shared__ float s_inv[256];
    __shared__ float lw[OW * 33];

    int slice = slice_base + (blockIdx.x >> 3);
    int iblk  = blockIdx.x & 7;
    const float* p = pos + (size_t)slice * NN * 3;
    int tid = threadIdx.x;

    for (int t = tid; t < OW * IW; t += 512)
        lw[(t >> 5) * 33 + (t & 31)] = lin_w[t];

    stage_geom(p, geom, tid, 512);

    int warp = tid >> 5;
    int lane = tid & 31;
    int g = lane >> 2, tg = lane & 3;
    unsigned odd = tg & 1, is3 = (tg == 3);
    int off = (tg & 1) * 8 + g;
    int row_lo = iblk * 256 + warp * 16 + g;
    int row_hi = row_lo + 8;

    float csl, csh;
    unsigned afl, afh, aflm, afhm;
    {
        float x = p[3 * row_lo], y = p[3 * row_lo + 1], z = p[3 * row_lo + 2];
        csl = C1 * (x * x + y * y + z * z);
        afl = make_afrag(x, y, z, tg);
        x = p[3 * row_hi]; y = p[3 * row_hi + 1]; z = p[3 * row_hi + 2];
        csh = C1 * (x * x + y * y + z * z);
        afh = make_afrag(x, y, z, tg);
        aflm = odd ? (afl & 0x0000FFFFu) : afl;
        afhm = odd ? (afh & 0x0000FFFFu) : afh;
    }
    __syncthreads();

    float a0l = 0.0f, a1l = 0.0f, a0h = 0.0f, a1h = 0.0f;
#pragma unroll 4
    for (int oct = 0; oct < 256; oct++) {
        unsigned b0, b1;
        geom_bfrag(geom, oct, off, is3, odd, b0, b1);
        float t0, t1, t2, t3;
        mma_f16_init(t0, t1, t2, t3, afl, afh, aflm, afhm, b0, b1,
                     csl, csl, csh, csh);
        a0l += ex2f(t0); a1l += ex2f(t1);
        a0h += ex2f(t2); a1h += ex2f(t3);
    }
    float accl = a0l + a1l;
    float acch = a0h + a1h;
    accl += __shfl_xor_sync(0xffffffffu, accl, 1);
    accl += __shfl_xor_sync(0xffffffffu, accl, 2);
    acch += __shfl_xor_sync(0xffffffffu, acch, 1);
    acch += __shfl_xor_sync(0xffffffffu, acch, 2);
    if (tg == 0) {
        float invl = 1.0f / (accl * accl);
        float invh = 1.0f / (acch * acch);
        s_inv[warp * 16 + g]     = invl;
        s_inv[warp * 16 + g + 8] = invh;
        inv_d2[slice * NN + row_lo] = invl;
        inv_d2[slice * NN + row_hi] = invh;
    }
    __syncthreads();

    // wl epilogue: this block's 256 nodes, two per iteration, packed fp16x2.
#pragma unroll 2
    for (int t = 0; t < 16; t += 2) {
        int nl  = warp * 16 + t;
        int j11 = iblk * 256 + nl;                 // even
        size_t gj = (size_t)slice * NN + j11;
        float wv0 = w[gj * IW + lane];
        float wv1 = w[(gj + 1) * IW + lane];
        float acc0 = 0.0f, acc1 = 0.0f;
#pragma unroll
        for (int k = 0; k < IW; k++) {
            float lwk = lw[lane * 33 + k];
            acc0 = fmaf(__shfl_sync(0xffffffffu, wv0, k), lwk, acc0);
            acc1 = fmaf(__shfl_sync(0xffffffffu, wv1, k), lwk, acc1);
        }
        acc0 *= s_inv[nl] * WLSCALE;
        acc1 *= s_inv[nl + 1] * WLSCALE;
        unsigned pk = pack_f16(acc0, acc1);        // lo = even j

        int chunk16 = j11 >> 4;
        int kk      = j11 & 15;                    // even
        int tg_d    = (kk >> 1) & 3;
        int h       = kk >> 3;
        int nb_d    = lane >> 3;                   // o octet
        int g_d     = lane & 7;                    // n within octet
        // new layout: [chunk16][half(nb>>1)][rlane(32)][word(4)]
        size_t addr = (((size_t)slice * 128 + chunk16) * 2 + (nb_d >> 1)) * 128
                    + (g_d * 4 + tg_d) * 4 + (nb_d & 1) * 2 + h;
        wlh[addr] = pk;
    }
}

// ---------------------------------------------------------------------------
// Pass C (hot): split-fp16 geometry MMA (distances) + fp16 product MMAs.
// 128 blocks x 256 thr per 8-slice chunk.
// smem: geom (32KB) | wls[2][2048] u32 (16KB) = 48KB -> 4 blocks/SM.
// ---------------------------------------------------------------------------
#define JTILE   128
#define NTILES  (NN / JTILE)

__global__ void __launch_bounds__(256) main_kernel(
    const float* __restrict__ pos, const unsigned* __restrict__ wlh,
    const float* __restrict__ inv_d2, const float* __restrict__ lin_b,
    float* __restrict__ out, int slice_base) {
    __shared__ unsigned geom[256 * 32];  // 32 KB
    __shared__ unsigned wls[2][2048];    // 2 x 8 KB

    int slice = slice_base + (blockIdx.x >> 4);
    int iblk  = blockIdx.x & 15;
    const float* p = pos + (size_t)slice * NN * 3;
    int tid = threadIdx.x;

    stage_geom(p, geom, tid, 256);

    int warp = tid >> 5;
    int lane = tid & 31;
    int g = lane >> 2, tg = lane & 3;
    unsigned odd = tg & 1, is3 = (tg == 3);
    int off = (tg & 1) * 8 + g;
    int row_lo = iblk * 128 + warp * 16 + g;
    int row_hi = row_lo + 8;

    float csl, csh;
    unsigned afl, afh, aflm, afhm;
    {
        float x = p[3 * row_lo], y = p[3 * row_lo + 1], z = p[3 * row_lo + 2];
        csl = C1 * (x * x + y * y + z * z);
        afl = make_afrag(x, y, z, tg);
        x = p[3 * row_hi]; y = p[3 * row_hi + 1]; z = p[3 * row_hi + 2];
        csh = C1 * (x * x + y * y + z * z);
        afh = make_afrag(x, y, z, tg);
        aflm = odd ? (afl & 0x0000FFFFu) : afl;
        afhm = odd ? (afh & 0x0000FFFFu) : afh;
    }

    const unsigned* wsrc = wlh + (size_t)slice * 32768;
    uint32_t wls_sm = (uint32_t)__cvta_generic_to_shared(&wls[0][0]);

    // prologue: tile 0 -> buffer 0 (256 thr x 2 x 16B = 8KB)
    {
        const uint4* src = (const uint4*)wsrc;
        cp_async16(wls_sm + tid * 16, src + tid);
        cp_async16(wls_sm + 4096 + tid * 16, src + tid + 256);
        asm volatile("cp.async.commit_group;");
    }

    float acc[16];
#pragma unroll
    for (int r = 0; r < 16; r++) acc[r] = 0.0f;

    for (int tile = 0; tile < NTILES; tile++) {
        int cur = tile & 1;
        asm volatile("cp.async.wait_group 0;");
        __syncthreads();   // buffer cur filled + geom staged (first iter)

        if (tile + 1 < NTILES) {
            const uint4* src = (const uint4*)(wsrc + (tile + 1) * 2048);
            uint32_t d = wls_sm + (cur ^ 1) * 8192 + tid * 16;
            cp_async16(d, src + tid);
            cp_async16(d + 4096, src + tid + 256);
            asm volatile("cp.async.commit_group;");
        }

        const unsigned* wbuf = wls[cur];
#pragma unroll
        for (int cc = 0; cc < JTILE / 16; cc++) {
            int oct0 = tile * (JTILE / 8) + 2 * cc;

            unsigned b0, b1;
            geom_bfrag(geom, oct0, off, is3, odd, b0, b1);
            float t0, t1, t2, t3;
            mma_f16_init(t0, t1, t2, t3, afl, afh, aflm, afhm, b0, b1,
                         csl, csl, csh, csh);

            geom_bfrag(geom, oct0 + 1, off, is3, odd, b0, b1);
            float u0, u1, u2, u3;
            mma_f16_init(u0, u1, u2, u3, afl, afh, aflm, afhm, b0, b1,
                         csl, csl, csh, csh);

            // product A-frags: geometry C layout == product A layout
            unsigned a0 = pack_f16(ex2f(t0), ex2f(t1));  // row_lo, k=2tg,2tg+1
            unsigned a1 = pack_f16(ex2f(t2), ex2f(t3));  // row_hi
            unsigned a2 = pack_f16(ex2f(u0), ex2f(u1));  // row_lo, k=+8
            unsigned a3 = pack_f16(ex2f(u2), ex2f(u3));  // row_hi

            // wl B-frags: two conflict-free LDS.128 (stride 16B per lane)
            uint4 b01 = ((const uint4*)(wbuf + cc * 256))[lane];
            uint4 b23 = ((const uint4*)(wbuf + cc * 256 + 128))[lane];

            mma_f16(acc + 0,  a0, a1, a2, a3, b01.x, b01.y);
            mma_f16(acc + 4,  a0, a1, a2, a3, b01.z, b01.w);
            mma_f16(acc + 8,  a0, a1, a2, a3, b23.x, b23.y);
            mma_f16(acc + 12, a0, a1, a2, a3, b23.z, b23.w);
        }
    }

    float invl = inv_d2[slice * NN + row_lo] * INV_WLSCALE;
    float invh = inv_d2[slice * NN + row_hi] * INV_WLSCALE;
    float* orow_lo = out + ((size_t)slice * NN + row_lo) * OW;
    float* orow_hi = out + ((size_t)slice * NN + row_hi) * OW;
#pragma unroll
    for (int nb = 0; nb < 4; nb++) {
        int col = nb * 8 + tg * 2;
        float lb0 = __ldg(lin_b + col);
        float lb1 = __ldg(lin_b + col + 1);
        float2 vlo = make_float2(fmaf(acc[nb * 4 + 0], invl, lb0),
                                 fmaf(acc[nb * 4 + 1], invl, lb1));
        float2 vhi = make_float2(fmaf(acc[nb * 4 + 2], invh, lb0),
                                 fmaf(acc[nb * 4 + 3], invh, lb1));
        *(float2*)(orow_lo + col) = vlo;
        *(float2*)(orow_hi + col) = vhi;
    }
}

// ---------------------------------------------------------------------------
// Launcher: 2-stream pipeline, deg chunk k -> main chunk k via events.
// Stream/event objects are host-side (no device allocation).
// ---------------------------------------------------------------------------
extern "C" void kernel_launch(void* const* d_in, const int* in_sizes, int n_in,
                              void* d_out, int out_size) {
    const float* positions = (const float*)d_in[0];
    const float* weights   = (const float*)d_in[1];
    const float* lin_w     = (const float*)d_in[2];
    const float* lin_b     = (const float*)d_in[3];
    float* out = (float*)d_out;

    int pos_elems = in_sizes[0];
    float* out_weights = out + pos_elems;

    float* inv_d2;
    unsigned* wlh;
    cudaGetSymbolAddress((void**)&inv_d2, g_inv_d2);
    cudaGetSymbolAddress((void**)&wlh, g_wlh);

    static cudaStream_t sD = nullptr, sM = nullptr;
    static cudaEvent_t eFork, eD[NCHUNK], eJoinD, eJoinM;
    if (!sD) {
        cudaStreamCreateWithFlags(&sD, cudaStreamNonBlocking);
        cudaStreamCreateWithFlags(&sM, cudaStreamNonBlocking);
        cudaEventCreateWithFlags(&eFork, cudaEventDisableTiming);
        for (int c = 0; c < NCHUNK; c++)
            cudaEventCreateWithFlags(&eD[c], cudaEventDisableTiming);
        cudaEventCreateWithFlags(&eJoinD, cudaEventDisableTiming);
        cudaEventCreateWithFlags(&eJoinM, cudaEventDisableTiming);
    }

    // fork from the (captured) default stream
    cudaEventRecord(eFork, 0);
    cudaStreamWaitEvent(sD, eFork, 0);
    cudaStreamWaitEvent(sM, eFork, 0);

    // positions passthrough overlaps with deg chunk 0
    cudaMemcpyAsync(out, positions, (size_t)pos_elems * sizeof(float),
                    cudaMemcpyDeviceToDevice, sM);

    for (int c = 0; c < NCHUNK; c++) {
        int base = c * SL_PER_CHUNK;
        deg_wl_kernel<<<SL_PER_CHUNK * 8, 512, 0, sD>>>(
            positions, weights, lin_w, inv_d2, wlh, base);
        cudaEventRecord(eD[c], sD);
        cudaStreamWaitEvent(sM, eD[c], 0);
        main_kernel<<<SL_PER_CHUNK * 16, 256, 0, sM>>>(
            positions, wlh, inv_d2, lin_b, out_weights, base);
    }

    // join both branches back to the default stream
    cudaEventRecord(eJoinD, sD);
    cudaEventRecord(eJoinM, sM);
    cudaStreamWaitEvent(0, eJoinD, 0);
    cudaStreamWaitEvent(0, eJoinM, 0);
}

// round 12
// speedup vs baseline: 1.5500x; 1.5500x over previous
#include <cuda_runtime.h>
#include <cuda_fp16.h>
#include <cstdint>

// Problem constants.
#define NSLICE 32      // B*KI = 8*4
#define NN     2048    // nodes per slice
#define IW     32
#define OW     32

// exp(-sq/2) = exp2(C1 * sq), C1 = -1/(2 ln 2)
#define C1   (-0.7213475204444817f)
#define M2C1 ( 1.4426950408889634f)   // -2*C1
#define WLSCALE    4096.0f
#define INV_WLSCALE (1.0f / 4096.0f)

// Scratch (device globals: allocation-free contract).
__device__ float g_inv_d2[NSLICE * NN];
// wl as packed fp16x2 (scaled), layout per chunk16:
// [slice][chunk16(128)][half(2)][rlane(32)][word(4)]
__device__ unsigned g_wlh[(size_t)NSLICE * 128 * 256];

// ---------------------------------------------------------------------------
// PTX helpers
// ---------------------------------------------------------------------------
__device__ __forceinline__ unsigned ex2h2(unsigned a) {   // 2 x fp16 exp2
    unsigned d; asm("ex2.approx.f16x2 %0, %1;" : "=r"(d) : "r"(a)); return d;
}
__device__ __forceinline__ unsigned pack_f16(float lo, float hi) {
    unsigned d;
    asm("cvt.rn.f16x2.f32 %0, %1, %2;" : "=r"(d) : "f"(hi), "f"(lo));
    return d;
}
__device__ __forceinline__ unsigned pack2h(__half lo, __half hi) {
    return ((unsigned)__half_as_ushort(hi) << 16) | __half_as_ushort(lo);
}
// product MMA accumulate form: C += A(16x16)*B(16x8), fp16 -> fp32
__device__ __forceinline__ void mma_f16(float* c, unsigned a0, unsigned a1,
                                        unsigned a2, unsigned a3,
                                        unsigned b0, unsigned b1) {
    asm volatile(
        "mma.sync.aligned.m16n8k16.row.col.f32.f16.f16.f32 "
        "{%0,%1,%2,%3}, {%4,%5,%6,%7}, {%8,%9}, {%0,%1,%2,%3};"
        : "+f"(c[0]), "+f"(c[1]), "+f"(c[2]), "+f"(c[3])
        : "r"(a0), "r"(a1), "r"(a2), "r"(a3), "r"(b0), "r"(b1));
}
// geometry MMA with separate C (init form): D = A*B + C
__device__ __forceinline__ void mma_f16_init(
    float& d0, float& d1, float& d2, float& d3,
    unsigned a0, unsigned a1, unsigned a2, unsigned a3,
    unsigned b0, unsigned b1,
    float c0, float c1, float c2, float c3) {
    asm volatile(
        "mma.sync.aligned.m16n8k16.row.col.f32.f16.f16.f32 "
        "{%0,%1,%2,%3}, {%4,%5,%6,%7}, {%8,%9}, {%10,%11,%12,%13};"
        : "=f"(d0), "=f"(d1), "=f"(d2), "=f"(d3)
        : "r"(a0), "r"(a1), "r"(a2), "r"(a3), "r"(b0), "r"(b1),
          "f"(c0), "f"(c1), "f"(c2), "f"(c3));
}
__device__ __forceinline__ void cp_async16(uint32_t dst, const void* src) {
    asm volatile("cp.async.cg.shared.global [%0], [%1], 16;" :: "r"(dst), "l"(src));
}

// ---------------------------------------------------------------------------
// Geometry staging: per node j, fp16 two-term splits packed as 4 u32 pairs:
//  pair0 = (xh, yh), pair1 = (zh, csh), pair2 = (xl, yl), pair3 = (zl, csl)
// layout geom[oct(256)][pair(4)][j8(8)] -> 32 u32 per octet (32 KB total).
// ---------------------------------------------------------------------------
__device__ __forceinline__ void stage_geom(const float* __restrict__ p,
                                           unsigned* geom, int tid, int nt) {
    for (int n = tid; n < NN; n += nt) {
        float x = p[3 * n + 0], y = p[3 * n + 1], z = p[3 * n + 2];
        float cs = C1 * (x * x + y * y + z * z);
        __half xh = __float2half_rn(x), yh = __float2half_rn(y);
        __half zh = __float2half_rn(z), ch = __float2half_rn(cs);
        float xl = x - __half2float(xh), yl = y - __half2float(yh);
        float zl = z - __half2float(zh), cl = cs - __half2float(ch);
        int base = ((n >> 3) << 5) + (n & 7);
        geom[base + 0]  = pack2h(xh, yh);
        geom[base + 8]  = pack2h(zh, ch);
        geom[base + 16] = pack_f16(xl, yl);
        geom[base + 24] = pack_f16(zl, cl);
    }
}

// Row-side A-fragment component for this thread's tg slot.
__device__ __forceinline__ unsigned make_afrag(float x, float y, float z, int tg) {
    float qx = M2C1 * x, qy = M2C1 * y, qz = M2C1 * z;
    __half qxh = __float2half_rn(qx), qyh = __float2half_rn(qy);
    __half qzh = __float2half_rn(qz);
    if (tg == 0) return pack2h(qxh, qyh);
    if (tg == 1) return pack2h(qzh, __float2half_rn(1.0f));
    float qxl = qx - __half2float(qxh), qyl = qy - __half2float(qyh);
    float qzl = qz - __half2float(qzh);
    if (tg == 2) return pack_f16(qxl, qyl);
    return pack_f16(qzl, 1.0f);
}

// Per-octet geometry B-fragment from packed pairs.
__device__ __forceinline__ void geom_bfrag(const unsigned* geom, int oct, int off,
                                           unsigned is3, unsigned odd,
                                           unsigned& b0, unsigned& b1) {
    unsigned pa = geom[oct * 32 + off];        // pair0 or pair1
    unsigned pb = geom[oct * 32 + 16 + off];   // pair2 or pair3
    b0 = is3 ? __byte_perm(pa, pb, 0x7610) : pa;   // tg3: (zh, csl)
    b1 = odd ? (pb & 0x0000FFFFu) : pb;            // odd tg: zero hi (cs slot)
}

#define ONES_H2 0x3C003C00u   // (1.0h, 1.0h)

// ---------------------------------------------------------------------------
// Pass A (fused): degrees via split-fp16 geometry MMA + f16x2 exp +
// ones-B fp16 sum-MMA (degree lands in fp32 c0/c2 directly), then wl epilogue.
// 256 blocks x 512 thr; block owns 256 rows.
// ---------------------------------------------------------------------------
__global__ void __launch_bounds__(512) deg_wl_kernel(
    const float* __restrict__ pos, const float* __restrict__ w,
    const float* __restrict__ lin_w, float* __restrict__ inv_d2,
    unsigned* __restrict__ wlh) {
    __shared__ unsigned geom[256 * 32];   // 32 KB
    __shared__ float s_inv[256];
    __shared__ float lw[OW * 33];

    int slice = blockIdx.x >> 3;
    int iblk  = blockIdx.x & 7;
    const float* p = pos + (size_t)slice * NN * 3;
    int tid = threadIdx.x;

    for (int t = tid; t < OW * IW; t += 512)
        lw[(t >> 5) * 33 + (t & 31)] = lin_w[t];

    stage_geom(p, geom, tid, 512);

    int warp = tid >> 5;
    int lane = tid & 31;
    int g = lane >> 2, tg = lane & 3;
    unsigned odd = tg & 1, is3 = (tg == 3);
    int off = (tg & 1) * 8 + g;
    int row_lo = iblk * 256 + warp * 16 + g;
    int row_hi = row_lo + 8;

    float csl, csh;
    unsigned afl, afh, aflm, afhm;
    {
        float x = p[3 * row_lo], y = p[3 * row_lo + 1], z = p[3 * row_lo + 2];
        csl = C1 * (x * x + y * y + z * z);
        afl = make_afrag(x, y, z, tg);
        x = p[3 * row_hi]; y = p[3 * row_hi + 1]; z = p[3 * row_hi + 2];
        csh = C1 * (x * x + y * y + z * z);
        afh = make_afrag(x, y, z, tg);
        aflm = odd ? (afl & 0x0000FFFFu) : afl;
        afhm = odd ? (afh & 0x0000FFFFu) : afh;
    }
    __syncthreads();

    float dacc[4] = {0.0f, 0.0f, 0.0f, 0.0f};
#pragma unroll 4
    for (int cc = 0; cc < 128; cc++) {
        int oct0 = 2 * cc;
        unsigned b0, b1;
        geom_bfrag(geom, oct0, off, is3, odd, b0, b1);
        float t0, t1, t2, t3;
        mma_f16_init(t0, t1, t2, t3, afl, afh, aflm, afhm, b0, b1,
                     csl, csl, csh, csh);
        geom_bfrag(geom, oct0 + 1, off, is3, odd, b0, b1);
        float u0, u1, u2, u3;
        mma_f16_init(u0, u1, u2, u3, afl, afh, aflm, afhm, b0, b1,
                     csl, csl, csh, csh);

        unsigned a0 = ex2h2(pack_f16(t0, t1));   // row_lo, k=2tg,2tg+1
        unsigned a1 = ex2h2(pack_f16(t2, t3));   // row_hi
        unsigned a2 = ex2h2(pack_f16(u0, u1));   // row_lo, k=+8
        unsigned a3 = ex2h2(pack_f16(u2, u3));   // row_hi

        mma_f16(dacc, a0, a1, a2, a3, ONES_H2, ONES_H2);
    }
    // dacc[0] = degree(row_lo), dacc[2] = degree(row_hi); all tg identical.
    if (tg == 0) {
        float invl = 1.0f / (dacc[0] * dacc[0]);
        float invh = 1.0f / (dacc[2] * dacc[2]);
        s_inv[warp * 16 + g]     = invl;
        s_inv[warp * 16 + g + 8] = invh;
        inv_d2[slice * NN + row_lo] = invl;
        inv_d2[slice * NN + row_hi] = invh;
    }
    __syncthreads();

    // wl epilogue: this block's 256 nodes, two per iteration, packed fp16x2.
#pragma unroll 2
    for (int t = 0; t < 16; t += 2) {
        int nl  = warp * 16 + t;
        int j11 = iblk * 256 + nl;                 // even
        size_t gj = (size_t)slice * NN + j11;
        float wv0 = w[gj * IW + lane];
        float wv1 = w[(gj + 1) * IW + lane];
        float acc0 = 0.0f, acc1 = 0.0f;
#pragma unroll
        for (int k = 0; k < IW; k++) {
            float lwk = lw[lane * 33 + k];
            acc0 = fmaf(__shfl_sync(0xffffffffu, wv0, k), lwk, acc0);
            acc1 = fmaf(__shfl_sync(0xffffffffu, wv1, k), lwk, acc1);
        }
        acc0 *= s_inv[nl] * WLSCALE;
        acc1 *= s_inv[nl + 1] * WLSCALE;
        unsigned pk = pack_f16(acc0, acc1);        // lo = even j

        int chunk16 = j11 >> 4;
        int kk      = j11 & 15;                    // even
        int tg_d    = (kk >> 1) & 3;
        int h       = kk >> 3;
        int nb_d    = lane >> 3;                   // o octet
        int g_d     = lane & 7;                    // n within octet
        size_t addr = (((size_t)slice * 128 + chunk16) * 2 + (nb_d >> 1)) * 128
                    + (g_d * 4 + tg_d) * 4 + (nb_d & 1) * 2 + h;
        wlh[addr] = pk;
    }
}

// ---------------------------------------------------------------------------
// Pass C (hot): split-fp16 geometry MMA + f16x2 exp + fp16 product MMAs.
// 512 blocks x 256 thr; smem 48KB -> 4 blocks/SM, one wave.
// ---------------------------------------------------------------------------
#define JTILE   128
#define NTILES  (NN / JTILE)

__global__ void __launch_bounds__(256) main_kernel(
    const float* __restrict__ pos, const unsigned* __restrict__ wlh,
    const float* __restrict__ inv_d2, const float* __restrict__ lin_b,
    float* __restrict__ out) {
    __shared__ unsigned geom[256 * 32];  // 32 KB
    __shared__ unsigned wls[2][2048];    // 2 x 8 KB

    int slice = blockIdx.x >> 4;
    int iblk  = blockIdx.x & 15;
    const float* p = pos + (size_t)slice * NN * 3;
    int tid = threadIdx.x;

    stage_geom(p, geom, tid, 256);

    int warp = tid >> 5;
    int lane = tid & 31;
    int g = lane >> 2, tg = lane & 3;
    unsigned odd = tg & 1, is3 = (tg == 3);
    int off = (tg & 1) * 8 + g;
    int row_lo = iblk * 128 + warp * 16 + g;
    int row_hi = row_lo + 8;

    float csl, csh;
    unsigned afl, afh, aflm, afhm;
    {
        float x = p[3 * row_lo], y = p[3 * row_lo + 1], z = p[3 * row_lo + 2];
        csl = C1 * (x * x + y * y + z * z);
        afl = make_afrag(x, y, z, tg);
        x = p[3 * row_hi]; y = p[3 * row_hi + 1]; z = p[3 * row_hi + 2];
        csh = C1 * (x * x + y * y + z * z);
        afh = make_afrag(x, y, z, tg);
        aflm = odd ? (afl & 0x0000FFFFu) : afl;
        afhm = odd ? (afh & 0x0000FFFFu) : afh;
    }

    const unsigned* wsrc = wlh + (size_t)slice * 32768;
    uint32_t wls_sm = (uint32_t)__cvta_generic_to_shared(&wls[0][0]);

    // prologue: tile 0 -> buffer 0 (256 thr x 2 x 16B = 8KB)
    {
        const uint4* src = (const uint4*)wsrc;
        cp_async16(wls_sm + tid * 16, src + tid);
        cp_async16(wls_sm + 4096 + tid * 16, src + tid + 256);
        asm volatile("cp.async.commit_group;");
    }

    float acc[16];
#pragma unroll
    for (int r = 0; r < 16; r++) acc[r] = 0.0f;

    for (int tile = 0; tile < NTILES; tile++) {
        int cur = tile & 1;
        asm volatile("cp.async.wait_group 0;");
        __syncthreads();   // buffer cur filled + geom staged (first iter)

        if (tile + 1 < NTILES) {
            const uint4* src = (const uint4*)(wsrc + (tile + 1) * 2048);
            uint32_t d = wls_sm + (cur ^ 1) * 8192 + tid * 16;
            cp_async16(d, src + tid);
            cp_async16(d + 4096, src + tid + 256);
            asm volatile("cp.async.commit_group;");
        }

        const unsigned* wbuf = wls[cur];
#pragma unroll
        for (int cc = 0; cc < JTILE / 16; cc++) {
            int oct0 = tile * (JTILE / 8) + 2 * cc;

            unsigned b0, b1;
            geom_bfrag(geom, oct0, off, is3, odd, b0, b1);
            float t0, t1, t2, t3;
            mma_f16_init(t0, t1, t2, t3, afl, afh, aflm, afhm, b0, b1,
                         csl, csl, csh, csh);

            geom_bfrag(geom, oct0 + 1, off, is3, odd, b0, b1);
            float u0, u1, u2, u3;
            mma_f16_init(u0, u1, u2, u3, afl, afh, aflm, afhm, b0, b1,
                         csl, csl, csh, csh);

            // pack args, f16x2 exp -> directly the product A-fragments
            unsigned a0 = ex2h2(pack_f16(t0, t1));  // row_lo, k=2tg,2tg+1
            unsigned a1 = ex2h2(pack_f16(t2, t3));  // row_hi
            unsigned a2 = ex2h2(pack_f16(u0, u1));  // row_lo, k=+8
            unsigned a3 = ex2h2(pack_f16(u2, u3));  // row_hi

            // wl B-frags: two conflict-free LDS.128 (stride 16B per lane)
            uint4 b01 = ((const uint4*)(wbuf + cc * 256))[lane];
            uint4 b23 = ((const uint4*)(wbuf + cc * 256 + 128))[lane];

            mma_f16(acc + 0,  a0, a1, a2, a3, b01.x, b01.y);
            mma_f16(acc + 4,  a0, a1, a2, a3, b01.z, b01.w);
            mma_f16(acc + 8,  a0, a1, a2, a3, b23.x, b23.y);
            mma_f16(acc + 12, a0, a1, a2, a3, b23.z, b23.w);
        }
    }

    float invl = inv_d2[slice * NN + row_lo] * INV_WLSCALE;
    float invh = inv_d2[slice * NN + row_hi] * INV_WLSCALE;
    float* orow_lo = out + ((size_t)slice * NN + row_lo) * OW;
    float* orow_hi = out + ((size_t)slice * NN + row_hi) * OW;
#pragma unroll
    for (int nb = 0; nb < 4; nb++) {
        int col = nb * 8 + tg * 2;
        float lb0 = __ldg(lin_b + col);
        float lb1 = __ldg(lin_b + col + 1);
        float2 vlo = make_float2(fmaf(acc[nb * 4 + 0], invl, lb0),
                                 fmaf(acc[nb * 4 + 1], invl, lb1));
        float2 vhi = make_float2(fmaf(acc[nb * 4 + 2], invh, lb0),
                                 fmaf(acc[nb * 4 + 3], invh, lb1));
        *(float2*)(orow_lo + col) = vlo;
        *(float2*)(orow_hi + col) = vhi;
    }
}

// ---------------------------------------------------------------------------
// Launcher: single stream, full grids (chunked multi-stream pipeline was a
// measured regression — wave-filling grids win).
// ---------------------------------------------------------------------------
extern "C" void kernel_launch(void* const* d_in, const int* in_sizes, int n_in,
                              void* d_out, int out_size) {
    const float* positions = (const float*)d_in[0];
    const float* weights   = (const float*)d_in[1];
    const float* lin_w     = (const float*)d_in[2];
    const float* lin_b     = (const float*)d_in[3];
    float* out = (float*)d_out;

    int pos_elems = in_sizes[0];
    float* out_weights = out + pos_elems;

    float* inv_d2;
    unsigned* wlh;
    cudaGetSymbolAddress((void**)&inv_d2, g_inv_d2);
    cudaGetSymbolAddress((void**)&wlh, g_wlh);

    cudaMemcpyAsync(out, positions, (size_t)pos_elems * sizeof(float),
                    cudaMemcpyDeviceToDevice);

    deg_wl_kernel<<<NSLICE * 8, 512>>>(positions, weights, lin_w, inv_d2, wlh);
    main_kernel<<<NSLICE * 16, 256>>>(positions, wlh, inv_d2, lin_b, out_weights);
}

// round 14
// speedup vs baseline: 1.5732x; 1.0150x over previous
#include <cuda_runtime.h>
#include <cuda_fp16.h>
#include <cstdint>

// Problem constants.
#define NSLICE 32      // B*KI = 8*4
#define NN     2048    // nodes per slice
#define IW     32
#define OW     32
#define NBLK   (NSLICE * 16)   // 512 blocks, 16 per slice
#define DYN_SMEM 49152         // geom (32KB) + wls (16KB)

// exp(-sq/2) = exp2(C1 * sq), C1 = -1/(2 ln 2)
#define C1   (-0.7213475204444817f)
#define M2C1 ( 1.4426950408889634f)   // -2*C1
#define WLSCALE    4096.0f
#define INV_WLSCALE (1.0f / 4096.0f)

// Scratch (device globals: allocation-free contract).
__device__ float g_inv_d2[NSLICE * NN];            // fallback mode only
__device__ unsigned g_wlh[(size_t)NSLICE * 128 * 256];
__device__ unsigned g_bar_ctr   = 0;
__device__ unsigned g_bar_sense = 0;

// ---------------------------------------------------------------------------
// PTX helpers
// ---------------------------------------------------------------------------
__device__ __forceinline__ unsigned ex2h2(unsigned a) {   // 2 x fp16 exp2
    unsigned d; asm("ex2.approx.f16x2 %0, %1;" : "=r"(d) : "r"(a)); return d;
}
__device__ __forceinline__ unsigned pack_f16(float lo, float hi) {
    unsigned d;
    asm("cvt.rn.f16x2.f32 %0, %1, %2;" : "=r"(d) : "f"(hi), "f"(lo));
    return d;
}
__device__ __forceinline__ unsigned pack2h(__half lo, __half hi) {
    return ((unsigned)__half_as_ushort(hi) << 16) | __half_as_ushort(lo);
}
__device__ __forceinline__ void mma_f16(float* c, unsigned a0, unsigned a1,
                                        unsigned a2, unsigned a3,
                                        unsigned b0, unsigned b1) {
    asm volatile(
        "mma.sync.aligned.m16n8k16.row.col.f32.f16.f16.f32 "
        "{%0,%1,%2,%3}, {%4,%5,%6,%7}, {%8,%9}, {%0,%1,%2,%3};"
        : "+f"(c[0]), "+f"(c[1]), "+f"(c[2]), "+f"(c[3])
        : "r"(a0), "r"(a1), "r"(a2), "r"(a3), "r"(b0), "r"(b1));
}
__device__ __forceinline__ void mma_f16_init(
    float& d0, float& d1, float& d2, float& d3,
    unsigned a0, unsigned a1, unsigned a2, unsigned a3,
    unsigned b0, unsigned b1,
    float c0, float c1, float c2, float c3) {
    asm volatile(
        "mma.sync.aligned.m16n8k16.row.col.f32.f16.f16.f32 "
        "{%0,%1,%2,%3}, {%4,%5,%6,%7}, {%8,%9}, {%10,%11,%12,%13};"
        : "=f"(d0), "=f"(d1), "=f"(d2), "=f"(d3)
        : "r"(a0), "r"(a1), "r"(a2), "r"(a3), "r"(b0), "r"(b1),
          "f"(c0), "f"(c1), "f"(c2), "f"(c3));
}
__device__ __forceinline__ void cp_async16(uint32_t dst, const void* src) {
    asm volatile("cp.async.cg.shared.global [%0], [%1], 16;" :: "r"(dst), "l"(src));
}

// ---------------------------------------------------------------------------
// Geometry staging: per node j, fp16 two-term splits packed as 4 u32 pairs.
// layout geom[oct(256)][pair(4)][j8(8)] -> 32 u32 per octet (32 KB).
// ---------------------------------------------------------------------------
__device__ __forceinline__ void stage_geom(const float* __restrict__ p,
                                           unsigned* geom, int tid) {
    for (int n = tid; n < NN; n += 256) {
        float x = p[3 * n + 0], y = p[3 * n + 1], z = p[3 * n + 2];
        float cs = C1 * (x * x + y * y + z * z);
        __half xh = __float2half_rn(x), yh = __float2half_rn(y);
        __half zh = __float2half_rn(z), ch = __float2half_rn(cs);
        float xl = x - __half2float(xh), yl = y - __half2float(yh);
        float zl = z - __half2float(zh), cl = cs - __half2float(ch);
        int base = ((n >> 3) << 5) + (n & 7);
        geom[base + 0]  = pack2h(xh, yh);
        geom[base + 8]  = pack2h(zh, ch);
        geom[base + 16] = pack_f16(xl, yl);
        geom[base + 24] = pack_f16(zl, cl);
    }
}

__device__ __forceinline__ unsigned make_afrag(float x, float y, float z, int tg) {
    float qx = M2C1 * x, qy = M2C1 * y, qz = M2C1 * z;
    __half qxh = __float2half_rn(qx), qyh = __float2half_rn(qy);
    __half qzh = __float2half_rn(qz);
    if (tg == 0) return pack2h(qxh, qyh);
    if (tg == 1) return pack2h(qzh, __float2half_rn(1.0f));
    float qxl = qx - __half2float(qxh), qyl = qy - __half2float(qyh);
    float qzl = qz - __half2float(qzh);
    if (tg == 2) return pack_f16(qxl, qyl);
    return pack_f16(qzl, 1.0f);
}

__device__ __forceinline__ void geom_bfrag(const unsigned* geom, int oct, int off,
                                           unsigned is3, unsigned odd,
                                           unsigned& b0, unsigned& b1) {
    unsigned pa = geom[oct * 32 + off];
    unsigned pb = geom[oct * 32 + 16 + off];
    b0 = is3 ? __byte_perm(pa, pb, 0x7610) : pa;
    b1 = odd ? (pb & 0x0000FFFFu) : pb;
}

// K A-fragments (fp16x2 exps) for a 16-row x 16-j chunk.
__device__ __forceinline__ void kfrags(
    const unsigned* geom, int oct0, int off, unsigned is3, unsigned odd,
    unsigned afl, unsigned afh, unsigned aflm, unsigned afhm,
    float csl, float csh,
    unsigned& a0, unsigned& a1, unsigned& a2, unsigned& a3) {
    unsigned b0, b1;
    geom_bfrag(geom, oct0, off, is3, odd, b0, b1);
    float t0, t1, t2, t3;
    mma_f16_init(t0, t1, t2, t3, afl, afh, aflm, afhm, b0, b1,
                 csl, csl, csh, csh);
    geom_bfrag(geom, oct0 + 1, off, is3, odd, b0, b1);
    float u0, u1, u2, u3;
    mma_f16_init(u0, u1, u2, u3, afl, afh, aflm, afhm, b0, b1,
                 csl, csl, csh, csh);
    a0 = ex2h2(pack_f16(t0, t1));
    a1 = ex2h2(pack_f16(t2, t3));
    a2 = ex2h2(pack_f16(u0, u1));
    a3 = ex2h2(pack_f16(u2, u3));
}

#define ONES_H2 0x3C003C00u   // (1.0h, 1.0h)
#define JTILE   128
#define NTILES  (NN / JTILE)

// ---------------------------------------------------------------------------
// Fused kernel. mode: 3 = deg+wl, grid barrier, main (all 512 blocks resident)
//               1 = deg+wl only (writes g_inv_d2)   [fallback]
//               2 = main only (reads g_inv_d2)      [fallback]
// 512 blocks x 256 thr; block owns 128 rows of one slice.
// Dyn smem: geom (32 KB) | wls 2x8 KB. Static: lw, s_inv, sense (~4.7 KB).
// ---------------------------------------------------------------------------
extern __shared__ unsigned dynsm[];

__global__ void __launch_bounds__(256, 4) fused_kernel(
    const float* __restrict__ pos, const float* __restrict__ w,
    const float* __restrict__ lin_w, const float* __restrict__ lin_b,
    float* __restrict__ out, int mode) {
    unsigned* geom = dynsm;             // 8192 u32 = 32 KB
    unsigned* wls  = dynsm + 8192;      // 2 x 2048 u32 = 16 KB
    __shared__ float lw[OW * 33];       // 4.2 KB
    __shared__ float s_inv[128];
    __shared__ unsigned s_sense;

    int slice = blockIdx.x >> 4;
    int iblk  = blockIdx.x & 15;
    const float* p = pos + (size_t)slice * NN * 3;
    int tid = threadIdx.x;

    if (tid == 0) s_sense = *(volatile unsigned*)&g_bar_sense;  // pre-arrival snapshot

    if (mode & 1)
        for (int t = tid; t < OW * IW; t += 256)
            lw[(t >> 5) * 33 + (t & 31)] = lin_w[t];

    stage_geom(p, geom, tid);

    int warp = tid >> 5;
    int lane = tid & 31;
    int g = lane >> 2, tg = lane & 3;
    unsigned odd = tg & 1, is3 = (tg == 3);
    int off = (tg & 1) * 8 + g;
    int row_lo = iblk * 128 + warp * 16 + g;
    int row_hi = row_lo + 8;

    float csl, csh;
    unsigned afl, afh, aflm, afhm;
    {
        float x = p[3 * row_lo], y = p[3 * row_lo + 1], z = p[3 * row_lo + 2];
        csl = C1 * (x * x + y * y + z * z);
        afl = make_afrag(x, y, z, tg);
        x = p[3 * row_hi]; y = p[3 * row_hi + 1]; z = p[3 * row_hi + 2];
        csh = C1 * (x * x + y * y + z * z);
        afh = make_afrag(x, y, z, tg);
        aflm = odd ? (afl & 0x0000FFFFu) : afl;
        afhm = odd ? (afh & 0x0000FFFFu) : afh;
    }

    if (mode == 2 && tid < 128)
        s_inv[tid] = g_inv_d2[slice * NN + iblk * 128 + tid];
    __syncthreads();   // geom, lw, s_sense (and s_inv in mode 2) ready

    if (mode & 1) {
        // ---- phase 1: degrees via sum-MMA ----
        float dacc[4] = {0.0f, 0.0f, 0.0f, 0.0f};
#pragma unroll 4
        for (int cc = 0; cc < 128; cc++) {
            unsigned a0, a1, a2, a3;
            kfrags(geom, 2 * cc, off, is3, odd, afl, afh, aflm, afhm,
                   csl, csh, a0, a1, a2, a3);
            mma_f16(dacc, a0, a1, a2, a3, ONES_H2, ONES_H2);
        }
        if (tg == 0) {
            float invl = 1.0f / (dacc[0] * dacc[0]);
            float invh = 1.0f / (dacc[2] * dacc[2]);
            s_inv[warp * 16 + g]     = invl;
            s_inv[warp * 16 + g + 8] = invh;
            if (mode == 1) {
                g_inv_d2[slice * NN + row_lo] = invl;
                g_inv_d2[slice * NN + row_hi] = invh;
            }
        }
        __syncthreads();

        // ---- wl epilogue: this block's 128 nodes ----
#pragma unroll 2
        for (int t = 0; t < 16; t += 2) {
            int nl  = warp * 16 + t;
            int j11 = iblk * 128 + nl;                 // even
            size_t gj = (size_t)slice * NN + j11;
            float wv0 = w[gj * IW + lane];
            float wv1 = w[(gj + 1) * IW + lane];
            float acc0 = 0.0f, acc1 = 0.0f;
#pragma unroll
            for (int k = 0; k < IW; k++) {
                float lwk = lw[lane * 33 + k];
                acc0 = fmaf(__shfl_sync(0xffffffffu, wv0, k), lwk, acc0);
                acc1 = fmaf(__shfl_sync(0xffffffffu, wv1, k), lwk, acc1);
            }
            acc0 *= s_inv[nl] * WLSCALE;
            acc1 *= s_inv[nl + 1] * WLSCALE;
            unsigned pk = pack_f16(acc0, acc1);

            int chunk16 = j11 >> 4;
            int kk      = j11 & 15;
            int tg_d    = (kk >> 1) & 3;
            int h       = kk >> 3;
            int nb_d    = lane >> 3;
            int g_d     = lane & 7;
            size_t addr = (((size_t)slice * 128 + chunk16) * 2 + (nb_d >> 1)) * 128
                        + (g_d * 4 + tg_d) * 4 + (nb_d & 1) * 2 + h;
            g_wlh[addr] = pk;
        }
    }

    if (mode == 3) {
        // ---- grid barrier (sense reversal; all 512 blocks resident) ----
        __threadfence();          // publish g_wlh
        __syncthreads();
        if (tid == 0) {
            if (atomicAdd(&g_bar_ctr, 1) == (unsigned)gridDim.x - 1) {
                g_bar_ctr = 0;
                __threadfence();
                *(volatile unsigned*)&g_bar_sense = s_sense ^ 1;
            } else {
                while (*(volatile unsigned*)&g_bar_sense == s_sense)
                    __nanosleep(64);
            }
        }
        __syncthreads();
        __threadfence();
    }

    if (mode & 2) {
        // ---- phase 2: product mainloop ----
        const unsigned* wsrc = g_wlh + (size_t)slice * 32768;
        uint32_t wls_sm = (uint32_t)__cvta_generic_to_shared(wls);
        {
            const uint4* src = (const uint4*)wsrc;
            cp_async16(wls_sm + tid * 16, src + tid);
            cp_async16(wls_sm + 4096 + tid * 16, src + tid + 256);
            asm volatile("cp.async.commit_group;");
        }

        float acc[16];
#pragma unroll
        for (int r = 0; r < 16; r++) acc[r] = 0.0f;

        for (int tile = 0; tile < NTILES; tile++) {
            int cur = tile & 1;
            asm volatile("cp.async.wait_group 0;");
            __syncthreads();

            if (tile + 1 < NTILES) {
                const uint4* src = (const uint4*)(wsrc + (tile + 1) * 2048);
                uint32_t d = wls_sm + (cur ^ 1) * 8192 + tid * 16;
                cp_async16(d, src + tid);
                cp_async16(d + 4096, src + tid + 256);
                asm volatile("cp.async.commit_group;");
            }

            const unsigned* wbuf = wls + cur * 2048;
#pragma unroll
            for (int cc = 0; cc < JTILE / 16; cc++) {
                unsigned a0, a1, a2, a3;
                kfrags(geom, tile * (JTILE / 8) + 2 * cc, off, is3, odd,
                       afl, afh, aflm, afhm, csl, csh, a0, a1, a2, a3);

                uint4 b01 = ((const uint4*)(wbuf + cc * 256))[lane];
                uint4 b23 = ((const uint4*)(wbuf + cc * 256 + 128))[lane];

                mma_f16(acc + 0,  a0, a1, a2, a3, b01.x, b01.y);
                mma_f16(acc + 4,  a0, a1, a2, a3, b01.z, b01.w);
                mma_f16(acc + 8,  a0, a1, a2, a3, b23.x, b23.y);
                mma_f16(acc + 12, a0, a1, a2, a3, b23.z, b23.w);
            }
        }

        float invl = s_inv[warp * 16 + g] * INV_WLSCALE;
        float invh = s_inv[warp * 16 + g + 8] * INV_WLSCALE;
        float* orow_lo = out + ((size_t)slice * NN + row_lo) * OW;
        float* orow_hi = out + ((size_t)slice * NN + row_hi) * OW;
#pragma unroll
        for (int nb = 0; nb < 4; nb++) {
            int col = nb * 8 + tg * 2;
            float lb0 = __ldg(lin_b + col);
            float lb1 = __ldg(lin_b + col + 1);
            float2 vlo = make_float2(fmaf(acc[nb * 4 + 0], invl, lb0),
                                     fmaf(acc[nb * 4 + 1], invl, lb1));
            float2 vhi = make_float2(fmaf(acc[nb * 4 + 2], invh, lb0),
                                     fmaf(acc[nb * 4 + 3], invh, lb1));
            *(float2*)(orow_lo + col) = vlo;
            *(float2*)(orow_hi + col) = vhi;
        }
    }
}

// ---------------------------------------------------------------------------
// Launcher: fused single-launch if all 512 blocks can be co-resident
// (required for the software grid barrier), else safe two-launch fallback.
// ---------------------------------------------------------------------------
extern "C" void kernel_launch(void* const* d_in, const int* in_sizes, int n_in,
                              void* d_out, int out_size) {
    const float* positions = (const float*)d_in[0];
    const float* weights   = (const float*)d_in[1];
    const float* lin_w     = (const float*)d_in[2];
    const float* lin_b     = (const float*)d_in[3];
    float* out = (float*)d_out;

    int pos_elems = in_sizes[0];
    float* out_weights = out + pos_elems;

    static int fused_ok = -1;
    if (fused_ok < 0) {
        cudaFuncSetAttribute(fused_kernel,
                             cudaFuncAttributeMaxDynamicSharedMemorySize,
                             DYN_SMEM);
        int occ = 0, nsm = 0;
        cudaOccupancyMaxActiveBlocksPerMultiprocessor(&occ, fused_kernel, 256,
                                                      DYN_SMEM);
        cudaDeviceGetAttribute(&nsm, cudaDevAttrMultiProcessorCount, 0);
        fused_ok = (occ * nsm >= NBLK) ? 1 : 0;
    }

    cudaMemcpyAsync(out, positions, (size_t)pos_elems * sizeof(float),
                    cudaMemcpyDeviceToDevice);

    if (fused_ok) {
        fused_kernel<<<NBLK, 256, DYN_SMEM>>>(positions, weights, lin_w, lin_b,
                                              out_weights, 3);
    } else {
        fused_kernel<<<NBLK, 256, DYN_SMEM>>>(positions, weights, lin_w, lin_b,
                                              out_weights, 1);
        fused_kernel<<<NBLK, 256, DYN_SMEM>>>(positions, weights, lin_w, lin_b,
                                              out_weights, 2);
    }
}

// round 16
// speedup vs baseline: 1.5787x; 1.0035x over previous
#include <cuda_runtime.h>
#include <cuda_fp16.h>
#include <cstdint>

// Problem constants.
#define NSLICE 32      // B*KI = 8*4
#define NN     2048    // nodes per slice
#define IW     32
#define OW     32
#define NBLK   (NSLICE * 8)    // 256 blocks, 8 per slice, 256 rows each
#define DYN_SMEM 49152         // geom (32KB) + wls (16KB)

// exp(-sq/2) = exp2(C1 * sq), C1 = -1/(2 ln 2)
#define C1   (-0.7213475204444817f)
#define M2C1 ( 1.4426950408889634f)   // -2*C1
#define WLSCALE    4096.0f
#define INV_WLSCALE (1.0f / 4096.0f)

// Scratch (device globals: allocation-free contract).
__device__ float g_inv_d2[NSLICE * NN];            // fallback mode only
__device__ unsigned g_wlh[(size_t)NSLICE * 128 * 256];
__device__ unsigned g_bar_ctr   = 0;
__device__ unsigned g_bar_sense = 0;

// ---------------------------------------------------------------------------
// PTX helpers
// ---------------------------------------------------------------------------
__device__ __forceinline__ unsigned ex2h2(unsigned a) {   // 2 x fp16 exp2
    unsigned d; asm("ex2.approx.f16x2 %0, %1;" : "=r"(d) : "r"(a)); return d;
}
__device__ __forceinline__ unsigned pack_f16(float lo, float hi) {
    unsigned d;
    asm("cvt.rn.f16x2.f32 %0, %1, %2;" : "=r"(d) : "f"(hi), "f"(lo));
    return d;
}
__device__ __forceinline__ unsigned pack2h(__half lo, __half hi) {
    return ((unsigned)__half_as_ushort(hi) << 16) | __half_as_ushort(lo);
}
__device__ __forceinline__ void mma_f16(float* c, unsigned a0, unsigned a1,
                                        unsigned a2, unsigned a3,
                                        unsigned b0, unsigned b1) {
    asm volatile(
        "mma.sync.aligned.m16n8k16.row.col.f32.f16.f16.f32 "
        "{%0,%1,%2,%3}, {%4,%5,%6,%7}, {%8,%9}, {%0,%1,%2,%3};"
        : "+f"(c[0]), "+f"(c[1]), "+f"(c[2]), "+f"(c[3])
        : "r"(a0), "r"(a1), "r"(a2), "r"(a3), "r"(b0), "r"(b1));
}
__device__ __forceinline__ void mma_f16_init(
    float& d0, float& d1, float& d2, float& d3,
    unsigned a0, unsigned a1, unsigned a2, unsigned a3,
    unsigned b0, unsigned b1,
    float c0, float c1, float c2, float c3) {
    asm volatile(
        "mma.sync.aligned.m16n8k16.row.col.f32.f16.f16.f32 "
        "{%0,%1,%2,%3}, {%4,%5,%6,%7}, {%8,%9}, {%10,%11,%12,%13};"
        : "=f"(d0), "=f"(d1), "=f"(d2), "=f"(d3)
        : "r"(a0), "r"(a1), "r"(a2), "r"(a3), "r"(b0), "r"(b1),
          "f"(c0), "f"(c1), "f"(c2), "f"(c3));
}
__device__ __forceinline__ void cp_async16(uint32_t dst, const void* src) {
    asm volatile("cp.async.cg.shared.global [%0], [%1], 16;" :: "r"(dst), "l"(src));
}

// ---------------------------------------------------------------------------
// Geometry staging: per node j, fp16 two-term splits packed as 4 u32 pairs.
// layout geom[oct(256)][pair(4)][j8(8)] -> 32 u32 per octet (32 KB).
// ---------------------------------------------------------------------------
__device__ __forceinline__ void stage_geom(const float* __restrict__ p,
                                           unsigned* geom, int tid) {
    for (int n = tid; n < NN; n += 256) {
        float x = p[3 * n + 0], y = p[3 * n + 1], z = p[3 * n + 2];
        float cs = C1 * (x * x + y * y + z * z);
        __half xh = __float2half_rn(x), yh = __float2half_rn(y);
        __half zh = __float2half_rn(z), ch = __float2half_rn(cs);
        float xl = x - __half2float(xh), yl = y - __half2float(yh);
        float zl = z - __half2float(zh), cl = cs - __half2float(ch);
        int base = ((n >> 3) << 5) + (n & 7);
        geom[base + 0]  = pack2h(xh, yh);
        geom[base + 8]  = pack2h(zh, ch);
        geom[base + 16] = pack_f16(xl, yl);
        geom[base + 24] = pack_f16(zl, cl);
    }
}

__device__ __forceinline__ unsigned make_afrag(float x, float y, float z, int tg) {
    float qx = M2C1 * x, qy = M2C1 * y, qz = M2C1 * z;
    __half qxh = __float2half_rn(qx), qyh = __float2half_rn(qy);
    __half qzh = __float2half_rn(qz);
    if (tg == 0) return pack2h(qxh, qyh);
    if (tg == 1) return pack2h(qzh, __float2half_rn(1.0f));
    float qxl = qx - __half2float(qxh), qyl = qy - __half2float(qyh);
    float qzl = qz - __half2float(qzh);
    if (tg == 2) return pack_f16(qxl, qyl);
    return pack_f16(qzl, 1.0f);
}

// Geometry B-fragments for an oct pair (shared by both row sets).
__device__ __forceinline__ void geom_bfrag2(const unsigned* geom, int oct0,
                                            int off, unsigned is3, unsigned odd,
                                            unsigned& b0a, unsigned& b1a,
                                            unsigned& b0b, unsigned& b1b) {
    unsigned pa0 = geom[oct0 * 32 + off];
    unsigned pb0 = geom[oct0 * 32 + 16 + off];
    unsigned pa1 = geom[oct0 * 32 + 32 + off];
    unsigned pb1 = geom[oct0 * 32 + 48 + off];
    b0a = is3 ? __byte_perm(pa0, pb0, 0x7610) : pa0;
    b1a = odd ? (pb0 & 0x0000FFFFu) : pb0;
    b0b = is3 ? __byte_perm(pa1, pb1, 0x7610) : pa1;
    b1b = odd ? (pb1 & 0x0000FFFFu) : pb1;
}

// K A-fragments (fp16x2 exps) for 16 rows x 16 j given preloaded B-frags.
__device__ __forceinline__ void kfrags2(
    unsigned b0a, unsigned b1a, unsigned b0b, unsigned b1b,
    unsigned afl, unsigned afh, unsigned aflm, unsigned afhm,
    float csl, float csh,
    unsigned& a0, unsigned& a1, unsigned& a2, unsigned& a3) {
    float t0, t1, t2, t3;
    mma_f16_init(t0, t1, t2, t3, afl, afh, aflm, afhm, b0a, b1a,
                 csl, csl, csh, csh);
    float u0, u1, u2, u3;
    mma_f16_init(u0, u1, u2, u3, afl, afh, aflm, afhm, b0b, b1b,
                 csl, csl, csh, csh);
    a0 = ex2h2(pack_f16(t0, t1));
    a1 = ex2h2(pack_f16(t2, t3));
    a2 = ex2h2(pack_f16(u0, u1));
    a3 = ex2h2(pack_f16(u2, u3));
}

#define ONES_H2 0x3C003C00u   // (1.0h, 1.0h)
#define JTILE   128
#define NTILES  (NN / JTILE)

// ---------------------------------------------------------------------------
// Fused kernel, fat-block variant. 256 blocks x 256 thr, 2 blocks/SM
// (128 regs/thread budget). Block owns 256 rows; warp owns TWO independent
// 16-row groups (rows r and r+128) sharing all B-fragment loads.
// mode: 3 = fused w/ grid barrier; 1 = deg+wl only; 2 = main only (fallback).
// ---------------------------------------------------------------------------
extern __shared__ unsigned dynsm[];

__global__ void __launch_bounds__(256, 2) fused_kernel(
    const float* __restrict__ pos, const float* __restrict__ w,
    const float* __restrict__ lin_w, const float* __restrict__ lin_b,
    float* __restrict__ out, int mode) {
    unsigned* geom = dynsm;             // 8192 u32 = 32 KB
    unsigned* wls  = dynsm + 8192;      // 2 x 2048 u32 = 16 KB
    __shared__ float lw[OW * 33];       // 4.2 KB
    __shared__ float s_inv[256];
    __shared__ unsigned s_sense;

    int slice = blockIdx.x >> 3;
    int iblk  = blockIdx.x & 7;
    int rbase = iblk * 256;
    const float* p = pos + (size_t)slice * NN * 3;
    int tid = threadIdx.x;

    if (tid == 0) s_sense = *(volatile unsigned*)&g_bar_sense;  // pre-arrival

    if (mode & 1)
        for (int t = tid; t < OW * IW; t += 256)
            lw[(t >> 5) * 33 + (t & 31)] = lin_w[t];

    stage_geom(p, geom, tid);

    int warp = tid >> 5;
    int lane = tid & 31;
    int g = lane >> 2, tg = lane & 3;
    unsigned odd = tg & 1, is3 = (tg == 3);
    int off = (tg & 1) * 8 + g;
    // Row set A: rows rbase + warp*16 + g (+8). Row set B: +128.
    int rA = rbase + warp * 16 + g;
    int rB = rA + 128;

    float cslA, cshA, cslB, cshB;
    unsigned aflA, afhA, aflmA, afhmA, aflB, afhB, aflmB, afhmB;
    {
        float x = p[3 * rA], y = p[3 * rA + 1], z = p[3 * rA + 2];
        cslA = C1 * (x * x + y * y + z * z);
        aflA = make_afrag(x, y, z, tg);
        x = p[3 * (rA + 8)]; y = p[3 * (rA + 8) + 1]; z = p[3 * (rA + 8) + 2];
        cshA = C1 * (x * x + y * y + z * z);
        afhA = make_afrag(x, y, z, tg);
        aflmA = odd ? (aflA & 0x0000FFFFu) : aflA;
        afhmA = odd ? (afhA & 0x0000FFFFu) : afhA;

        x = p[3 * rB]; y = p[3 * rB + 1]; z = p[3 * rB + 2];
        cslB = C1 * (x * x + y * y + z * z);
        aflB = make_afrag(x, y, z, tg);
        x = p[3 * (rB + 8)]; y = p[3 * (rB + 8) + 1]; z = p[3 * (rB + 8) + 2];
        cshB = C1 * (x * x + y * y + z * z);
        afhB = make_afrag(x, y, z, tg);
        aflmB = odd ? (aflB & 0x0000FFFFu) : aflB;
        afhmB = odd ? (afhB & 0x0000FFFFu) : afhB;
    }

    if (mode == 2)
        s_inv[tid] = g_inv_d2[slice * NN + rbase + tid];
    __syncthreads();   // geom, lw, s_sense (and s_inv in mode 2) ready

    if (mode & 1) {
        // ---- phase 1: degrees via sum-MMA, both row sets ----
        float daccA[4] = {0.0f, 0.0f, 0.0f, 0.0f};
        float daccB[4] = {0.0f, 0.0f, 0.0f, 0.0f};
#pragma unroll 4
        for (int cc = 0; cc < 128; cc++) {
            unsigned b0a, b1a, b0b, b1b;
            geom_bfrag2(geom, 2 * cc, off, is3, odd, b0a, b1a, b0b, b1b);
            unsigned a0, a1, a2, a3;
            kfrags2(b0a, b1a, b0b, b1b, aflA, afhA, aflmA, afhmA,
                    cslA, cshA, a0, a1, a2, a3);
            mma_f16(daccA, a0, a1, a2, a3, ONES_H2, ONES_H2);
            kfrags2(b0a, b1a, b0b, b1b, aflB, afhB, aflmB, afhmB,
                    cslB, cshB, a0, a1, a2, a3);
            mma_f16(daccB, a0, a1, a2, a3, ONES_H2, ONES_H2);
        }
        if (tg == 0) {
            float iA0 = 1.0f / (daccA[0] * daccA[0]);
            float iA1 = 1.0f / (daccA[2] * daccA[2]);
            float iB0 = 1.0f / (daccB[0] * daccB[0]);
            float iB1 = 1.0f / (daccB[2] * daccB[2]);
            s_inv[warp * 16 + g]           = iA0;
            s_inv[warp * 16 + g + 8]       = iA1;
            s_inv[warp * 16 + g + 128]     = iB0;
            s_inv[warp * 16 + g + 136]     = iB1;
            if (mode == 1) {
                g_inv_d2[slice * NN + rA]       = iA0;
                g_inv_d2[slice * NN + rA + 8]   = iA1;
                g_inv_d2[slice * NN + rB]       = iB0;
                g_inv_d2[slice * NN + rB + 8]   = iB1;
            }
        }
        __syncthreads();

        // ---- wl epilogue: this block's 256 nodes (32 per warp) ----
#pragma unroll 2
        for (int t = 0; t < 32; t += 2) {
            int nl  = warp * 32 + t;
            int j11 = rbase + nl;                      // even
            size_t gj = (size_t)slice * NN + j11;
            float wv0 = w[gj * IW + lane];
            float wv1 = w[(gj + 1) * IW + lane];
            float acc0 = 0.0f, acc1 = 0.0f;
#pragma unroll
            for (int k = 0; k < IW; k++) {
                float lwk = lw[lane * 33 + k];
                acc0 = fmaf(__shfl_sync(0xffffffffu, wv0, k), lwk, acc0);
                acc1 = fmaf(__shfl_sync(0xffffffffu, wv1, k), lwk, acc1);
            }
            acc0 *= s_inv[nl] * WLSCALE;
            acc1 *= s_inv[nl + 1] * WLSCALE;
            unsigned pk = pack_f16(acc0, acc1);

            int chunk16 = j11 >> 4;
            int kk      = j11 & 15;
            int tg_d    = (kk >> 1) & 3;
            int h       = kk >> 3;
            int nb_d    = lane >> 3;
            int g_d     = lane & 7;
            size_t addr = (((size_t)slice * 128 + chunk16) * 2 + (nb_d >> 1)) * 128
                        + (g_d * 4 + tg_d) * 4 + (nb_d & 1) * 2 + h;
            g_wlh[addr] = pk;
        }
    }

    if (mode == 3) {
        // ---- grid barrier (sense reversal; all 256 blocks resident) ----
        __threadfence();          // publish g_wlh
        __syncthreads();
        if (tid == 0) {
            if (atomicAdd(&g_bar_ctr, 1) == (unsigned)gridDim.x - 1) {
                g_bar_ctr = 0;
                __threadfence();
                *(volatile unsigned*)&g_bar_sense = s_sense ^ 1;
            } else {
                while (*(volatile unsigned*)&g_bar_sense == s_sense)
                    __nanosleep(64);
            }
        }
        __syncthreads();
        __threadfence();
    }

    if (mode & 2) {
        // ---- phase 2: product mainloop, both row sets ----
        const unsigned* wsrc = g_wlh + (size_t)slice * 32768;
        uint32_t wls_sm = (uint32_t)__cvta_generic_to_shared(wls);
        {
            const uint4* src = (const uint4*)wsrc;
            cp_async16(wls_sm + tid * 16, src + tid);
            cp_async16(wls_sm + 4096 + tid * 16, src + tid + 256);
            asm volatile("cp.async.commit_group;");
        }

        float accA[16], accB[16];
#pragma unroll
        for (int r = 0; r < 16; r++) { accA[r] = 0.0f; accB[r] = 0.0f; }

        for (int tile = 0; tile < NTILES; tile++) {
            int cur = tile & 1;
            asm volatile("cp.async.wait_group 0;");
            __syncthreads();

            if (tile + 1 < NTILES) {
                const uint4* src = (const uint4*)(wsrc + (tile + 1) * 2048);
                uint32_t d = wls_sm + (cur ^ 1) * 8192 + tid * 16;
                cp_async16(d, src + tid);
                cp_async16(d + 4096, src + tid + 256);
                asm volatile("cp.async.commit_group;");
            }

            const unsigned* wbuf = wls + cur * 2048;
#pragma unroll
            for (int cc = 0; cc < JTILE / 16; cc++) {
                unsigned b0a, b1a, b0b, b1b;
                geom_bfrag2(geom, tile * (JTILE / 8) + 2 * cc, off, is3, odd,
                            b0a, b1a, b0b, b1b);

                uint4 w01 = ((const uint4*)(wbuf + cc * 256))[lane];
                uint4 w23 = ((const uint4*)(wbuf + cc * 256 + 128))[lane];

                unsigned a0, a1, a2, a3;
                kfrags2(b0a, b1a, b0b, b1b, aflA, afhA, aflmA, afhmA,
                        cslA, cshA, a0, a1, a2, a3);
                mma_f16(accA + 0,  a0, a1, a2, a3, w01.x, w01.y);
                mma_f16(accA + 4,  a0, a1, a2, a3, w01.z, w01.w);
                mma_f16(accA + 8,  a0, a1, a2, a3, w23.x, w23.y);
                mma_f16(accA + 12, a0, a1, a2, a3, w23.z, w23.w);

                kfrags2(b0a, b1a, b0b, b1b, aflB, afhB, aflmB, afhmB,
                        cslB, cshB, a0, a1, a2, a3);
                mma_f16(accB + 0,  a0, a1, a2, a3, w01.x, w01.y);
                mma_f16(accB + 4,  a0, a1, a2, a3, w01.z, w01.w);
                mma_f16(accB + 8,  a0, a1, a2, a3, w23.x, w23.y);
                mma_f16(accB + 12, a0, a1, a2, a3, w23.z, w23.w);
            }
        }

        float iA0 = s_inv[warp * 16 + g] * INV_WLSCALE;
        float iA1 = s_inv[warp * 16 + g + 8] * INV_WLSCALE;
        float iB0 = s_inv[warp * 16 + g + 128] * INV_WLSCALE;
        float iB1 = s_inv[warp * 16 + g + 136] * INV_WLSCALE;
        float* oA0 = out + ((size_t)slice * NN + rA) * OW;
        float* oA1 = out + ((size_t)slice * NN + rA + 8) * OW;
        float* oB0 = out + ((size_t)slice * NN + rB) * OW;
        float* oB1 = out + ((size_t)slice * NN + rB + 8) * OW;
#pragma unroll
        for (int nb = 0; nb < 4; nb++) {
            int col = nb * 8 + tg * 2;
            float lb0 = __ldg(lin_b + col);
            float lb1 = __ldg(lin_b + col + 1);
            *(float2*)(oA0 + col) = make_float2(
                fmaf(accA[nb * 4 + 0], iA0, lb0), fmaf(accA[nb * 4 + 1], iA0, lb1));
            *(float2*)(oA1 + col) = make_float2(
                fmaf(accA[nb * 4 + 2], iA1, lb0), fmaf(accA[nb * 4 + 3], iA1, lb1));
            *(float2*)(oB0 + col) = make_float2(
                fmaf(accB[nb * 4 + 0], iB0, lb0), fmaf(accB[nb * 4 + 1], iB0, lb1));
            *(float2*)(oB1 + col) = make_float2(
                fmaf(accB[nb * 4 + 2], iB1, lb0), fmaf(accB[nb * 4 + 3], iB1, lb1));
        }
    }
}

// ---------------------------------------------------------------------------
// Launcher: fused single-launch if all 256 blocks co-resident (checked with
// the ACTUAL compiled occupancy), else safe two-launch fallback.
// ---------------------------------------------------------------------------
extern "C" void kernel_launch(void* const* d_in, const int* in_sizes, int n_in,
                              void* d_out, int out_size) {
    const float* positions = (const float*)d_in[0];
    const float* weights   = (const float*)d_in[1];
    const float* lin_w     = (const float*)d_in[2];
    const float* lin_b     = (const float*)d_in[3];
    float* out = (float*)d_out;

    int pos_elems = in_sizes[0];
    float* out_weights = out + pos_elems;

    static int fused_ok = -1;
    if (fused_ok < 0) {
        cudaFuncSetAttribute(fused_kernel,
                             cudaFuncAttributeMaxDynamicSharedMemorySize,
                             DYN_SMEM);
        int occ = 0, nsm = 0;
        cudaOccupancyMaxActiveBlocksPerMultiprocessor(&occ, fused_kernel, 256,
                                                      DYN_SMEM);
        cudaDeviceGetAttribute(&nsm, cudaDevAttrMultiProcessorCount, 0);
        fused_ok = (occ * nsm >= NBLK) ? 1 : 0;
    }

    cudaMemcpyAsync(out, positions, (size_t)pos_elems * sizeof(float),
                    cudaMemcpyDeviceToDevice);

    if (fused_ok) {
        fused_kernel<<<NBLK, 256, DYN_SMEM>>>(positions, weights, lin_w, lin_b,
                                              out_weights, 3);
    } else {
        fused_kernel<<<NBLK, 256, DYN_SMEM>>>(positions, weights, lin_w, lin_b,
                                              out_weights, 1);
        fused_kernel<<<NBLK, 256, DYN_SMEM>>>(positions, weights, lin_w, lin_b,
                                              out_weights, 2);
    }
}